// round 8
// baseline (speedup 1.0000x reference)
#include <cuda_runtime.h>

// T=2048, B=1024, H=50, 4H=200. Only batch row B-1 reaches the output
// (reference takes hs[:, -1, :] on the batch axis) and the recurrence is
// batch-independent -> single length-2048 sequence, H=50, on ONE SM.
#define TT 2048
#define BB 1024
#define HH 50
#define NTHREADS 128   // 4 warps, 1 per SMSP; lane pair 2u/2u+1 owns unit u

// Per-timestep hidden history; output dot handled in parallel epilogue.
__device__ float g_hs[TT * HH];

typedef unsigned long long ull;

__device__ __forceinline__ ull ffma2(ull a, ull b, ull c) {
    ull d;
    asm("fma.rn.f32x2 %0, %1, %2, %3;" : "=l"(d) : "l"(a), "l"(b), "l"(c));
    return d;
}
__device__ __forceinline__ ull fadd2(ull a, ull b) {
    ull d;
    asm("add.rn.f32x2 %0, %1, %2;" : "=l"(d) : "l"(a), "l"(b));
    return d;
}
__device__ __forceinline__ ull fmul2(ull a, ull b) {
    ull d;
    asm("mul.rn.f32x2 %0, %1, %2;" : "=l"(d) : "l"(a), "l"(b));
    return d;
}
__device__ __forceinline__ float tanh_fast(float x) {
    float r;
    asm("tanh.approx.f32 %0, %1;" : "=f"(r) : "f"(x));
    return r;
}
__device__ __forceinline__ float f2lo(ull v) { union { ull u; float2 f; } w; w.u = v; return w.f.x; }
__device__ __forceinline__ float f2hi(ull v) { union { ull u; float2 f; } w; w.u = v; return w.f.y; }
__device__ __forceinline__ ull pack2(float a, float b) {
    union { ull u; float2 f; } w; w.f.x = a; w.f.y = b; return w.u;
}

__global__ __launch_bounds__(NTHREADS, 1)
void lstm_seq_kernel(const float* __restrict__ x,      // (T, B, 1)
                     const float* __restrict__ W_ih,   // (4H, 1)
                     const float* __restrict__ W_hh,   // (4H, H)
                     const float* __restrict__ b_ih,
                     const float* __restrict__ b_hh,
                     const float* __restrict__ W_lin,  // (1, H)
                     const float* __restrict__ b_lin,
                     float* __restrict__ out)          // T floats
{
    __shared__ __align__(16) float h_s[2][56];  // double buffer
    __shared__ float xcol[TT];

    const int j    = threadIdx.x;
    const int half = j & 1;                 // 0: gates (i,g)   1: gates (f,o)
    const int u    = j >> 1;                // unit 0..63 (>=50 redundant)
    const int uc   = (u < HH) ? u : (HH - 1);
    // rowA: i (even) / f (odd) -- always sigmoid
    // rowB: g (even, tanh) / o (odd, sigmoid)
    const int rowA = half ? (HH + uc)     : uc;
    const int rowB = half ? (3 * HH + uc) : (2 * HH + uc);

    for (int t = j; t < TT; t += NTHREADS) xcol[t] = x[t * BB + (BB - 1)];
    if (j < 56) { h_s[0][j] = 0.0f; h_s[1][j] = 0.0f; }

    // Two weight rows per thread, packed f32x2; fold the sigmoid's 1/2
    // argument scaling into the weights/bias so activation = tanh + fma.
    ull wpA[25], wpB[25];
    float bsumA, bsumB, wihA, wihB;
    {
        const ull* ra = reinterpret_cast<const ull*>(W_hh + rowA * HH);
        const ull* rb = reinterpret_cast<const ull*>(W_hh + rowB * HH);
        const ull s05 = pack2(0.5f, 0.5f);
        const ull sB  = half ? s05 : pack2(1.0f, 1.0f);
        #pragma unroll
        for (int k = 0; k < 25; k++) {
            wpA[k] = fmul2(ra[k], s05);   // rowA always sigmoid
            wpB[k] = fmul2(rb[k], sB);    // rowB: sigmoid only on odd lanes
        }
        bsumA = 0.5f * (b_ih[rowA] + b_hh[rowA]);
        wihA  = 0.5f * W_ih[rowA];
        float sb = half ? 0.5f : 1.0f;
        bsumB = sb * (b_ih[rowB] + b_hh[rowB]);
        wihB  = sb * W_ih[rowB];
    }
    const float amulB = half ? 0.5f : 1.0f;   // post-tanh for rowB
    const float aaddB = half ? 0.5f : 0.0f;

    float c = 0.0f;                            // live on odd lanes only
    __syncthreads();

    #pragma unroll 1
    for (int t2 = 0; t2 < TT; t2 += 2) {
        #pragma unroll
        for (int s = 0; s < 2; s++) {
            const int t = t2 + s;
            const float* hsrc = h_s[s];
            float*       hdst = h_s[s ^ 1];
            const float  xv   = xcol[t];
            const float preA0 = fmaf(xv, wihA, bsumA);
            const float preB0 = fmaf(xv, wihB, bsumB);

            // --- two 50-dots sharing one h load; 4 accumulators each ---
            ull aA[4] = {0ull, 0ull, 0ull, 0ull};
            ull aB[4] = {0ull, 0ull, 0ull, 0ull};
            const ulonglong2* h4 = reinterpret_cast<const ulonglong2*>(hsrc);
            #pragma unroll
            for (int k = 0; k < 6; k++) {      // 6 x 4 = 24 packed pairs
                ulonglong2 p0 = h4[2 * k];
                ulonglong2 p1 = h4[2 * k + 1];
                aA[0] = ffma2(wpA[4 * k],     p0.x, aA[0]);
                aA[1] = ffma2(wpA[4 * k + 1], p0.y, aA[1]);
                aA[2] = ffma2(wpA[4 * k + 2], p1.x, aA[2]);
                aA[3] = ffma2(wpA[4 * k + 3], p1.y, aA[3]);
                aB[0] = ffma2(wpB[4 * k],     p0.x, aB[0]);
                aB[1] = ffma2(wpB[4 * k + 1], p0.y, aB[1]);
                aB[2] = ffma2(wpB[4 * k + 2], p1.x, aB[2]);
                aB[3] = ffma2(wpB[4 * k + 3], p1.y, aB[3]);
            }
            {
                ull hl = reinterpret_cast<const ull*>(hsrc)[24];
                aA[0] = ffma2(wpA[24], hl, aA[0]);
                aB[0] = ffma2(wpB[24], hl, aB[0]);
            }
            ull rA = fadd2(fadd2(aA[0], aA[1]), fadd2(aA[2], aA[3]));
            ull rB = fadd2(fadd2(aB[0], aB[1]), fadd2(aB[2], aB[3]));
            float preA = preA0 + (f2lo(rA) + f2hi(rA));
            float preB = preB0 + (f2lo(rB) + f2hi(rB));

            // activations (scaling already folded into pre)
            float gA = tanh_fast(preA);               // i (even) / f (odd)
            float gB = tanh_fast(preB);               // g (even) / o (odd)
            float aAv = fmaf(gA, 0.5f, 0.5f);         // sigmoid finish
            float aBv = fmaf(gB, amulB, aaddB);       // tanh (even) / sigmoid (odd)

            // single shuffle: even lane ships p = i*g to its odd partner
            float pv  = aAv * aBv;                    // meaningful on even lane
            float got = __shfl_xor_sync(0xffffffffu, pv, 1, 32);

            if (half) {                                // odd lane owns c, h
                c = fmaf(aAv, c, got);                 // c = f*c + i*g
                float hn = aBv * tanh_fast(c);         // h = o*tanh(c)
                if (u < HH) {
                    hdst[u] = hn;
                    g_hs[t * HH + u] = hn;             // fire-and-forget
                }
            }
            __syncthreads();
        }
    }

    // Epilogue: out[t] = dot(h_t, W_lin) + b_lin, parallel over t.
    const float bl = b_lin[0];
    for (int t = j; t < TT; t += NTHREADS) {
        float s = bl;
        #pragma unroll
        for (int k = 0; k < HH; k++) s += g_hs[t * HH + k] * W_lin[k];
        out[t] = s;
    }
}

extern "C" void kernel_launch(void* const* d_in, const int* in_sizes, int n_in,
                              void* d_out, int out_size) {
    const float* x     = (const float*)d_in[0];
    const float* W_ih  = (const float*)d_in[1];
    const float* W_hh  = (const float*)d_in[2];
    const float* b_ih  = (const float*)d_in[3];
    const float* b_hh  = (const float*)d_in[4];
    const float* W_lin = (const float*)d_in[5];
    const float* b_lin = (const float*)d_in[6];
    lstm_seq_kernel<<<1, NTHREADS>>>(x, W_ih, W_hh, b_ih, b_hh, W_lin, b_lin,
                                     (float*)d_out);
}